// round 13
// baseline (speedup 1.0000x reference)
#include <cuda_runtime.h>
#include <cstdint>

#define NU 100000
#define NE 1600000
#define NB 16384
#define D  128
#define SCAN_B 98   // ceil(NU / 1024)

typedef unsigned long long u64;

// ---- static scratch (no allocations allowed) ----
static __device__ int   g_rowptr[NU + 1];
static __device__ int   g_cursor[NU];
static __device__ int   g_esrc[NE];
static __device__ int   g_bsum[SCAN_B];
static __device__ int   g_boff[SCAN_B];
static __device__ float g_h1 [(size_t)NU * D];   // layer-1 user output
static __device__ float g_hn [(size_t)NU * D];   // layer-1 neighbor mean
static __device__ float g_hn2[(size_t)NB * D];   // layer-2 neighbor mean
static __device__ float g_acc[(size_t)NU * D];   // partial-GEMM accumulator
static __device__ float g_hi [(size_t)(2 * NB) * D];  // item layer-1 output

// ---------------- packed f32x2 helpers ----------------
__device__ __forceinline__ u64 dup2(float x) {
    u64 r; asm("mov.b64 %0, {%1, %1};" : "=l"(r) : "f"(x)); return r;
}
__device__ __forceinline__ void ffma2(u64& d, u64 a, u64 b) {
    asm("fma.rn.f32x2 %0, %1, %2, %0;" : "+l"(d) : "l"(a), "l"(b));
}
__device__ __forceinline__ float2 unpk(u64 v) {
    float2 r; asm("mov.b64 {%0, %1}, %2;" : "=f"(r.x), "=f"(r.y) : "l"(v)); return r;
}

// ---------------- CSR build ----------------
__global__ void k_zero() {
    int i = blockIdx.x * blockDim.x + threadIdx.x;
    if (i < NU) g_cursor[i] = 0;
}

__global__ void k_count(const int* __restrict__ dst) {
    int i = blockIdx.x * blockDim.x + threadIdx.x;   // NE/16 threads
    if (i < NE / 16) {
#pragma unroll
        for (int q = 0; q < 4; q++) {
            int4 d = ((const int4*)dst)[4 * i + q];
            atomicAdd(&g_cursor[d.x], 1); atomicAdd(&g_cursor[d.y], 1);
            atomicAdd(&g_cursor[d.z], 1); atomicAdd(&g_cursor[d.w], 1);
        }
    }
}

__global__ __launch_bounds__(1024) void k_scan_local() {
    __shared__ int sh[1024];
    const int t = threadIdx.x;
    const int i = blockIdx.x * 1024 + t;
    int c = (i < NU) ? g_cursor[i] : 0;
    int val = c;
    sh[t] = val;
    __syncthreads();
#pragma unroll
    for (int off = 1; off < 1024; off <<= 1) {
        int tmp = (t >= off) ? sh[t - off] : 0;
        __syncthreads();
        val += tmp;
        sh[t] = val;
        __syncthreads();
    }
    if (i < NU) g_rowptr[i] = val - c;
    if (t == 1023) g_bsum[blockIdx.x] = val;
}

__global__ __launch_bounds__(128) void k_scan_top() {
    __shared__ int sh[128];
    const int t = threadIdx.x;
    int v = (t < SCAN_B) ? g_bsum[t] : 0;
    int val = v;
    sh[t] = val;
    __syncthreads();
#pragma unroll
    for (int off = 1; off < 128; off <<= 1) {
        int tmp = (t >= off) ? sh[t - off] : 0;
        __syncthreads();
        val += tmp;
        sh[t] = val;
        __syncthreads();
    }
    if (t < SCAN_B) g_boff[t] = val - v;
}

__global__ void k_scan_add() {
    int i = blockIdx.x * blockDim.x + threadIdx.x;
    if (i < NU) {
        int r = g_rowptr[i] + g_boff[i >> 10];
        g_rowptr[i] = r;
        g_cursor[i] = r;
    }
    if (i == 0) g_rowptr[NU] = NE;
}

__global__ void k_scatter(const int* __restrict__ src, const int* __restrict__ dst) {
    int i = blockIdx.x * blockDim.x + threadIdx.x;   // NE/16 threads
    if (i < NE / 16) {
#pragma unroll
        for (int q = 0; q < 4; q++) {
            int4 d = ((const int4*)dst)[4 * i + q];
            int4 s = ((const int4*)src)[4 * i + q];
            int p0 = atomicAdd(&g_cursor[d.x], 1);
            int p1 = atomicAdd(&g_cursor[d.y], 1);
            int p2 = atomicAdd(&g_cursor[d.z], 1);
            int p3 = atomicAdd(&g_cursor[d.w], 1);
            g_esrc[p0] = s.x; g_esrc[p1] = s.y;
            g_esrc[p2] = s.z; g_esrc[p3] = s.w;
        }
    }
}

// ---------------- high-occupancy neighbor-mean aggregation ----------------
__device__ __forceinline__ void agg_row(
    const float* __restrict__ table, int row, int lane, float* __restrict__ dstv)
{
    int beg = g_rowptr[row], end = g_rowptr[row + 1];
    int deg = end - beg;
    float4 a = make_float4(0.f, 0.f, 0.f, 0.f);
    for (int base = 0; base < deg; base += 32) {
        int rem = deg - base;
        int n = rem < 32 ? rem : 32;
        int myi = (lane < n) ? g_esrc[beg + base + lane] : 0;
        int j = 0;
        for (; j + 8 <= n; j += 8) {
            int s0 = __shfl_sync(0xffffffffu, myi, j + 0);
            int s1 = __shfl_sync(0xffffffffu, myi, j + 1);
            int s2 = __shfl_sync(0xffffffffu, myi, j + 2);
            int s3 = __shfl_sync(0xffffffffu, myi, j + 3);
            int s4 = __shfl_sync(0xffffffffu, myi, j + 4);
            int s5 = __shfl_sync(0xffffffffu, myi, j + 5);
            int s6 = __shfl_sync(0xffffffffu, myi, j + 6);
            int s7 = __shfl_sync(0xffffffffu, myi, j + 7);
            float4 x0 = ((const float4*)(table + (size_t)s0 * D))[lane];
            float4 x1 = ((const float4*)(table + (size_t)s1 * D))[lane];
            float4 x2 = ((const float4*)(table + (size_t)s2 * D))[lane];
            float4 x3 = ((const float4*)(table + (size_t)s3 * D))[lane];
            float4 x4 = ((const float4*)(table + (size_t)s4 * D))[lane];
            float4 x5 = ((const float4*)(table + (size_t)s5 * D))[lane];
            float4 x6 = ((const float4*)(table + (size_t)s6 * D))[lane];
            float4 x7 = ((const float4*)(table + (size_t)s7 * D))[lane];
            a.x += ((x0.x + x1.x) + (x2.x + x3.x)) + ((x4.x + x5.x) + (x6.x + x7.x));
            a.y += ((x0.y + x1.y) + (x2.y + x3.y)) + ((x4.y + x5.y) + (x6.y + x7.y));
            a.z += ((x0.z + x1.z) + (x2.z + x3.z)) + ((x4.z + x5.z) + (x6.z + x7.z));
            a.w += ((x0.w + x1.w) + (x2.w + x3.w)) + ((x4.w + x5.w) + (x6.w + x7.w));
        }
        for (; j < n; j++) {
            int s = __shfl_sync(0xffffffffu, myi, j);
            float4 x = ((const float4*)(table + (size_t)s * D))[lane];
            a.x += x.x; a.y += x.y; a.z += x.z; a.w += x.w;
        }
    }
    float inv = 1.f / fmaxf((float)deg, 1.f);
    a.x *= inv; a.y *= inv; a.z *= inv; a.w *= inv;
    ((float4*)dstv)[lane] = a;
}

__global__ __launch_bounds__(256) void k_agg1(const float* __restrict__ feat) {
    int row  = (blockIdx.x * blockDim.x + threadIdx.x) >> 5;
    int lane = threadIdx.x & 31;
    if (row < NU) agg_row(feat, row, lane, g_hn + (size_t)row * D);
}

__global__ __launch_bounds__(256) void k_agg2(const int* __restrict__ users) {
    int b    = (blockIdx.x * blockDim.x + threadIdx.x) >> 5;
    int lane = threadIdx.x & 31;
    if (b < NB) agg_row(g_h1, users[b], lane, g_hn2 + (size_t)b * D);
}

// ---------------- FFMA2 GEMM core (two-phase W staging, 3 CTAs/SM) ----------------
// smem (floats): sW[8192] (64 k-rows of W), sB[128], sX[64*128]  = 66048 bytes
#define GM_SMEM ((8192 + 128 + 64 * D) * (int)sizeof(float))

// stage one k-half of W (64 rows x 128 cols)
__device__ __forceinline__ void stage_w_half(const float* __restrict__ W, float* sW, int tid) {
    const float4* g = (const float4*)W;
    float4* s = (float4*)sW;
#pragma unroll
    for (int i = 0; i < 8; i++) s[tid + i * 256] = g[tid + i * 256];
}

// full-K GEMM with two W-staging phases; accumulators persist in registers.
__device__ __forceinline__ void gemm_one8_2p(
    const float* sX, float* sW, const float* __restrict__ W,
    int tid, int lr0, int lane, u64* acc0, u64* acc1)
{
#pragma unroll
    for (int j = 0; j < 8; j++) { acc0[j] = 0ull; acc1[j] = 0ull; }
#pragma unroll
    for (int kh = 0; kh < 2; kh++) {
        __syncthreads();                    // prior phase done reading sW (and sX staged)
        stage_w_half(W + kh * 64 * D, sW, tid);
        __syncthreads();
        const float* sXh = sX + kh * 64;
#pragma unroll 4
        for (int k = 0; k < 64; k += 2) {
            ulonglong2 wa = *(const ulonglong2*)(sW + k * D + lane * 4);
            ulonglong2 wb = *(const ulonglong2*)(sW + (k + 1) * D + lane * 4);
#pragma unroll
            for (int j = 0; j < 8; j++) {
                float2 x2 = *(const float2*)(sXh + (lr0 + j) * D + k);
                u64 xx0 = dup2(x2.x), xx1 = dup2(x2.y);
                ffma2(acc0[j], xx0, wa.x); ffma2(acc1[j], xx0, wa.y);
                ffma2(acc0[j], xx1, wb.x); ffma2(acc1[j], xx1, wb.y);
            }
        }
    }
}

__device__ __forceinline__ float epi4(u64 a0, u64 a1, float4 pa, float4 b4, float4& v) {
    float2 p01 = unpk(a0), p23 = unpk(a1);
    float t0 = p01.x + pa.x + b4.x, t1 = p01.y + pa.y + b4.y;
    float t2 = p23.x + pa.z + b4.z, t3 = p23.y + pa.w + b4.w;
    t0 = t0 > 0.f ? t0 : 0.2f * t0;
    t1 = t1 > 0.f ? t1 : 0.2f * t1;
    t2 = t2 > 0.f ? t2 : 0.2f * t2;
    t3 = t3 > 0.f ? t3 : 0.2f * t3;
    v = make_float4(t0, t1, t2, t3);
    return t0 * t0 + t1 * t1 + t2 * t2 + t3 * t3;
}

// ---------------- dense1 pass A: g_acc = feat @ Ws ----------------
__global__ __launch_bounds__(256, 3) void k_d1a(
    const float* __restrict__ feat, const float* __restrict__ Ws)
{
    extern __shared__ float sm[];
    float* sW = sm;
    float* sX = sm + 8192 + 128;
    const int tid = threadIdx.x, warp = tid >> 5, lane = tid & 31;
    const int lr0 = warp * 8;
    const int r0 = blockIdx.x * 64;
#pragma unroll
    for (int j = 0; j < 8; j++) {
        int row = r0 + lr0 + j;
        ((float4*)(sX + (lr0 + j) * D))[lane] = (row < NU)
            ? ((const float4*)(feat + (size_t)row * D))[lane]
            : make_float4(0.f, 0.f, 0.f, 0.f);
    }
    u64 acc0[8], acc1[8];
    gemm_one8_2p(sX, sW, Ws, tid, lr0, lane, acc0, acc1);
#pragma unroll
    for (int j = 0; j < 8; j++) {
        int row = r0 + lr0 + j;
        if (row < NU) {
            float2 p01 = unpk(acc0[j]), p23 = unpk(acc1[j]);
            ((float4*)(g_acc + (size_t)row * D))[lane] =
                make_float4(p01.x, p01.y, p23.x, p23.y);
        }
    }
}

// ---------------- dense1 pass B ----------------
__global__ __launch_bounds__(256, 3) void k_d1b(
    const float* __restrict__ Wn, const float* __restrict__ bias)
{
    extern __shared__ float sm[];
    float* sW = sm;
    float* sB = sm + 8192;
    float* sX = sm + 8192 + 128;
    const int tid = threadIdx.x, warp = tid >> 5, lane = tid & 31;
    if (tid < 32) ((float4*)sB)[tid] = ((const float4*)bias)[tid];
    const int lr0 = warp * 8;
    const int r0 = blockIdx.x * 64;
#pragma unroll
    for (int j = 0; j < 8; j++) {
        int row = r0 + lr0 + j;
        ((float4*)(sX + (lr0 + j) * D))[lane] = (row < NU)
            ? ((const float4*)(g_hn + (size_t)row * D))[lane]
            : make_float4(0.f, 0.f, 0.f, 0.f);
    }
    u64 acc0[8], acc1[8];
    gemm_one8_2p(sX, sW, Wn, tid, lr0, lane, acc0, acc1);

    float4 b4 = ((const float4*)sB)[lane];
    float4 v[8]; float ss[8];
#pragma unroll
    for (int j = 0; j < 8; j++) {
        int row = r0 + lr0 + j;
        float4 pa = (row < NU) ? ((const float4*)(g_acc + (size_t)row * D))[lane]
                               : make_float4(0.f, 0.f, 0.f, 0.f);
        ss[j] = epi4(acc0[j], acc1[j], pa, b4, v[j]);
    }
#pragma unroll
    for (int off = 16; off; off >>= 1) {
#pragma unroll
        for (int j = 0; j < 8; j++) ss[j] += __shfl_xor_sync(0xffffffffu, ss[j], off);
    }
#pragma unroll
    for (int j = 0; j < 8; j++) {
        int row = r0 + lr0 + j;
        if (row < NU) {
            float sc = 1.f / fmaxf(sqrtf(ss[j]), 1e-12f);
            ((float4*)(g_h1 + (size_t)row * D))[lane] =
                make_float4(v[j].x * sc, v[j].y * sc, v[j].z * sc, v[j].w * sc);
        }
    }
}

// ---------------- dense2 pass A ----------------
__global__ __launch_bounds__(256, 3) void k_d2a(
    const float* __restrict__ ufeat, const int* __restrict__ users,
    const float* __restrict__ Ws, float* __restrict__ out)
{
    extern __shared__ float sm[];
    float* sW = sm;
    float* sX = sm + 8192 + 128;
    const int tid = threadIdx.x, warp = tid >> 5, lane = tid & 31;
    const int lr0 = warp * 8;
    const int r0 = blockIdx.x * 64;
#pragma unroll
    for (int j = 0; j < 8; j++) {
        int b = r0 + lr0 + j;
        int u = users[b];
        float4 x4 = ((const float4*)(g_h1 + (size_t)u * D))[lane];
        ((float4*)(sX + (lr0 + j) * D))[lane] = x4;
        ((float4*)(out + (size_t)b * 384))[lane]       = ((const float4*)(ufeat + (size_t)u * D))[lane];
        ((float4*)(out + (size_t)b * 384 + 128))[lane] = x4;
    }
    u64 acc0[8], acc1[8];
    gemm_one8_2p(sX, sW, Ws, tid, lr0, lane, acc0, acc1);
#pragma unroll
    for (int j = 0; j < 8; j++) {
        int b = r0 + lr0 + j;
        float2 p01 = unpk(acc0[j]), p23 = unpk(acc1[j]);
        ((float4*)(g_acc + (size_t)b * D))[lane] = make_float4(p01.x, p01.y, p23.x, p23.y);
    }
}

// ---------------- dense2 pass B ----------------
__global__ __launch_bounds__(256, 3) void k_d2b(
    const float* __restrict__ Wn, const float* __restrict__ bias, float* __restrict__ out)
{
    extern __shared__ float sm[];
    float* sW = sm;
    float* sB = sm + 8192;
    float* sX = sm + 8192 + 128;
    const int tid = threadIdx.x, warp = tid >> 5, lane = tid & 31;
    if (tid < 32) ((float4*)sB)[tid] = ((const float4*)bias)[tid];
    const int lr0 = warp * 8;
    const int r0 = blockIdx.x * 64;
#pragma unroll
    for (int j = 0; j < 8; j++) {
        int b = r0 + lr0 + j;
        ((float4*)(sX + (lr0 + j) * D))[lane] =
            ((const float4*)(g_hn2 + (size_t)b * D))[lane];
    }
    u64 acc0[8], acc1[8];
    gemm_one8_2p(sX, sW, Wn, tid, lr0, lane, acc0, acc1);

    float4 b4 = ((const float4*)sB)[lane];
    float4 v[8]; float ss[8];
#pragma unroll
    for (int j = 0; j < 8; j++) {
        int b = r0 + lr0 + j;
        float4 pa = ((const float4*)(g_acc + (size_t)b * D))[lane];
        ss[j] = epi4(acc0[j], acc1[j], pa, b4, v[j]);
    }
#pragma unroll
    for (int off = 16; off; off >>= 1) {
#pragma unroll
        for (int j = 0; j < 8; j++) ss[j] += __shfl_xor_sync(0xffffffffu, ss[j], off);
    }
#pragma unroll
    for (int j = 0; j < 8; j++) {
        float sc = 1.f / fmaxf(sqrtf(ss[j]), 1e-12f);
        int b = r0 + lr0 + j;
        ((float4*)(out + (size_t)b * 384 + 256))[lane] =
            make_float4(v[j].x * sc, v[j].y * sc, v[j].z * sc, v[j].w * sc);
    }
}

// ---------------- item tower pass 1 ----------------
__global__ __launch_bounds__(256, 3) void k_it1(
    const float* __restrict__ ifeat, const int* __restrict__ pos, const int* __restrict__ neg,
    const float* __restrict__ W0, const float* __restrict__ b0, float* __restrict__ out)
{
    extern __shared__ float sm[];
    float* sW = sm;
    float* sB = sm + 8192;
    float* sX = sm + 8192 + 128;
    const int tid = threadIdx.x, warp = tid >> 5, lane = tid & 31;
    if (tid < 32) ((float4*)sB)[tid] = ((const float4*)b0)[tid];
    const int lr0 = warp * 8;
    const int r0 = blockIdx.x * 64;
#pragma unroll
    for (int j = 0; j < 8; j++) {
        int rr = r0 + lr0 + j;
        int idx = (rr < NB) ? pos[rr] : neg[rr - NB];
        float4 x4 = ((const float4*)(ifeat + (size_t)idx * D))[lane];
        ((float4*)(sX + (lr0 + j) * D))[lane] = x4;
        ((float4*)(out + (size_t)(NB + rr) * 384))[lane] = x4;   // seg 0
    }
    u64 acc0[8], acc1[8];
    gemm_one8_2p(sX, sW, W0, tid, lr0, lane, acc0, acc1);

    float4 b4 = ((const float4*)sB)[lane];
    const float4 z4 = make_float4(0.f, 0.f, 0.f, 0.f);
    float4 v[8]; float ss[8];
#pragma unroll
    for (int j = 0; j < 8; j++) ss[j] = epi4(acc0[j], acc1[j], z4, b4, v[j]);
#pragma unroll
    for (int off = 16; off; off >>= 1) {
#pragma unroll
        for (int j = 0; j < 8; j++) ss[j] += __shfl_xor_sync(0xffffffffu, ss[j], off);
    }
#pragma unroll
    for (int j = 0; j < 8; j++) {
        float sc = 1.f / fmaxf(sqrtf(ss[j]), 1e-12f);
        int rr = r0 + lr0 + j;
        float4 o = make_float4(v[j].x * sc, v[j].y * sc, v[j].z * sc, v[j].w * sc);
        ((float4*)(g_hi + (size_t)rr * D))[lane] = o;
        ((float4*)(out + (size_t)(NB + rr) * 384 + 128))[lane] = o;  // seg 1
    }
}

// ---------------- item tower pass 2 ----------------
__global__ __launch_bounds__(256, 3) void k_it2(
    const float* __restrict__ W1, const float* __restrict__ b1, float* __restrict__ out)
{
    extern __shared__ float sm[];
    float* sW = sm;
    float* sB = sm + 8192;
    float* sX = sm + 8192 + 128;
    const int tid = threadIdx.x, warp = tid >> 5, lane = tid & 31;
    if (tid < 32) ((float4*)sB)[tid] = ((const float4*)b1)[tid];
    const int lr0 = warp * 8;
    const int r0 = blockIdx.x * 64;
#pragma unroll
    for (int j = 0; j < 8; j++) {
        int rr = r0 + lr0 + j;
        ((float4*)(sX + (lr0 + j) * D))[lane] =
            ((const float4*)(g_hi + (size_t)rr * D))[lane];
    }
    u64 acc0[8], acc1[8];
    gemm_one8_2p(sX, sW, W1, tid, lr0, lane, acc0, acc1);

    float4 b4 = ((const float4*)sB)[lane];
    const float4 z4 = make_float4(0.f, 0.f, 0.f, 0.f);
    float4 v[8]; float ss[8];
#pragma unroll
    for (int j = 0; j < 8; j++) ss[j] = epi4(acc0[j], acc1[j], z4, b4, v[j]);
#pragma unroll
    for (int off = 16; off; off >>= 1) {
#pragma unroll
        for (int j = 0; j < 8; j++) ss[j] += __shfl_xor_sync(0xffffffffu, ss[j], off);
    }
#pragma unroll
    for (int j = 0; j < 8; j++) {
        float sc = 1.f / fmaxf(sqrtf(ss[j]), 1e-12f);
        int rr = r0 + lr0 + j;
        ((float4*)(out + (size_t)(NB + rr) * 384 + 256))[lane] =
            make_float4(v[j].x * sc, v[j].y * sc, v[j].z * sc, v[j].w * sc);
    }
}

// ---------------- launch (fork/join schedule) ----------------
extern "C" void kernel_launch(void* const* d_in, const int* in_sizes, int n_in,
                              void* d_out, int out_size) {
    const int*   src   = (const int*)d_in[0];
    const int*   dst   = (const int*)d_in[1];
    const int*   users = (const int*)d_in[2];
    const int*   pos   = (const int*)d_in[3];
    const int*   neg   = (const int*)d_in[4];
    const float* ufeat = (const float*)d_in[5];
    const float* ifeat = (const float*)d_in[6];
    const float* Ws0   = (const float*)d_in[7];
    const float* Wn0   = (const float*)d_in[8];
    const float* bu0   = (const float*)d_in[9];
    const float* Wi0   = (const float*)d_in[10];
    const float* bi0   = (const float*)d_in[11];
    const float* Ws1   = (const float*)d_in[12];
    const float* Wn1   = (const float*)d_in[13];
    const float* bu1   = (const float*)d_in[14];
    const float* Wi1   = (const float*)d_in[15];
    const float* bi1   = (const float*)d_in[16];
    float* out = (float*)d_out;

    (void)cudaFuncSetAttribute(k_d1a, cudaFuncAttributeMaxDynamicSharedMemorySize, GM_SMEM);
    (void)cudaFuncSetAttribute(k_d1b, cudaFuncAttributeMaxDynamicSharedMemorySize, GM_SMEM);
    (void)cudaFuncSetAttribute(k_d2a, cudaFuncAttributeMaxDynamicSharedMemorySize, GM_SMEM);
    (void)cudaFuncSetAttribute(k_d2b, cudaFuncAttributeMaxDynamicSharedMemorySize, GM_SMEM);
    (void)cudaFuncSetAttribute(k_it1, cudaFuncAttributeMaxDynamicSharedMemorySize, GM_SMEM);
    (void)cudaFuncSetAttribute(k_it2, cudaFuncAttributeMaxDynamicSharedMemorySize, GM_SMEM);

    const int GD1 = (NU + 63) / 64;     // 1563
    const int GD2 = NB / 64;            // 256
    const int GIT = (2 * NB) / 64;      // 512

    static cudaStream_t sA = 0;
    static cudaEvent_t evFork = 0, evAgg1 = 0, evIt1 = 0, evD1b = 0, evD2a = 0;
    static int inited = 0;
    if (!inited) {
        if (cudaStreamCreateWithFlags(&sA, cudaStreamNonBlocking) != cudaSuccess) sA = 0;
        if (cudaEventCreateWithFlags(&evFork, cudaEventDisableTiming) != cudaSuccess) evFork = 0;
        if (cudaEventCreateWithFlags(&evAgg1, cudaEventDisableTiming) != cudaSuccess) evAgg1 = 0;
        if (cudaEventCreateWithFlags(&evIt1,  cudaEventDisableTiming) != cudaSuccess) evIt1 = 0;
        if (cudaEventCreateWithFlags(&evD1b,  cudaEventDisableTiming) != cudaSuccess) evD1b = 0;
        if (cudaEventCreateWithFlags(&evD2a,  cudaEventDisableTiming) != cudaSuccess) evD2a = 0;
        inited = 1;
    }
    const bool par = (sA && evFork && evAgg1 && evIt1 && evD1b && evD2a);

    if (par) {
        cudaEventRecord(evFork, 0);
        cudaStreamWaitEvent(sA, evFork, 0);

        // chain A (sA): it1 -> d1a -> [agg1] -> d1b -> d2a
        k_it1       <<<GIT, 256, GM_SMEM, sA>>>(ifeat, pos, neg, Wi0, bi0, out);
        cudaEventRecord(evIt1, sA);
        k_d1a       <<<GD1, 256, GM_SMEM, sA>>>(ufeat, Ws0);

        // chain B (default): CSR -> agg1
        k_zero      <<<(NU + 255) / 256, 256>>>();
        k_count     <<<(NE / 16 + 255) / 256, 256>>>(dst);
        k_scan_local<<<SCAN_B, 1024>>>();
        k_scan_top  <<<1, 128>>>();
        k_scan_add  <<<(NU + 255) / 256, 256>>>();
        k_scatter   <<<(NE / 16 + 255) / 256, 256>>>(src, dst);
        k_agg1      <<<(NU * 32 + 255) / 256, 256>>>(ufeat);
        cudaEventRecord(evAgg1, 0);

        // it2 fills idle time on default stream (needs only it1)
        cudaStreamWaitEvent(0, evIt1, 0);
        k_it2       <<<GIT, 256, GM_SMEM>>>(Wi1, bi1, out);

        // chain A continues
        cudaStreamWaitEvent(sA, evAgg1, 0);
        k_d1b       <<<GD1, 256, GM_SMEM, sA>>>(Wn0, bu0);
        cudaEventRecord(evD1b, sA);
        k_d2a       <<<GD2, 256, GM_SMEM, sA>>>(ufeat, users, Ws1, out);
        cudaEventRecord(evD2a, sA);

        // default: agg2 concurrent with d2a
        cudaStreamWaitEvent(0, evD1b, 0);
        k_agg2      <<<(NB * 32) / 256, 256>>>(users);

        // join
        cudaStreamWaitEvent(0, evD2a, 0);
        k_d2b       <<<GD2, 256, GM_SMEM>>>(Wn1, bu1, out);
    } else {
        // serial fallback
        k_zero      <<<(NU + 255) / 256, 256>>>();
        k_count     <<<(NE / 16 + 255) / 256, 256>>>(dst);
        k_it1       <<<GIT, 256, GM_SMEM>>>(ifeat, pos, neg, Wi0, bi0, out);
        k_d1a       <<<GD1, 256, GM_SMEM>>>(ufeat, Ws0);
        k_scan_local<<<SCAN_B, 1024>>>();
        k_scan_top  <<<1, 128>>>();
        k_scan_add  <<<(NU + 255) / 256, 256>>>();
        k_scatter   <<<(NE / 16 + 255) / 256, 256>>>(src, dst);
        k_it2       <<<GIT, 256, GM_SMEM>>>(Wi1, bi1, out);
        k_agg1      <<<(NU * 32 + 255) / 256, 256>>>(ufeat);
        k_d1b       <<<GD1, 256, GM_SMEM>>>(Wn0, bu0);
        k_agg2      <<<(NB * 32) / 256, 256>>>(users);
        k_d2a       <<<GD2, 256, GM_SMEM>>>(ufeat, users, Ws1, out);
        k_d2b       <<<GD2, 256, GM_SMEM>>>(Wn1, bu1, out);
    }
}